// round 2
// baseline (speedup 1.0000x reference)
#include <cuda_runtime.h>
#include <cuda_bf16.h>

// Problem constants
constexpr int SEQ   = 1024;
constexpr int BATCH = 8;
constexpr int DM    = 1024;
constexpr int NH    = 16;
constexpr int HD    = 64;     // DM / NH
constexpr int FF    = 4096;
constexpr int SB    = SEQ * BATCH;   // 8192 rows
constexpr float EPS = 1e-5f;

// ---------------------------------------------------------------------------
// Scratch (device globals — no allocation allowed)
// ---------------------------------------------------------------------------
__device__ float g_qkv[(size_t)SB * 3 * DM];              //  96 MB  [S*B, 3D]
__device__ float g_scores[(size_t)BATCH * NH * SEQ * SEQ];// 536 MB  [b,h,s,t]
__device__ float g_ctx[(size_t)SB * DM];                  //  32 MB  [S,B,D]
__device__ float g_x[(size_t)SB * DM];                    //  32 MB  post-LN1
__device__ float g_h1[(size_t)SB * FF];                   // 128 MB  FFN hidden
__device__ float g_tmp[(size_t)SB * DM];                  //  32 MB  pre-LN scratch

// ---------------------------------------------------------------------------
// Generic tiled GEMM:  C[m,n] = scale * sum_k A[m,k] * B(.,.)  (+bias)(+resid)(relu)
//   B_KN == false : B is [N, K] row-major (weights, "W^T" GEMM) — both K-contig
//   B_KN == true  : B is [K, N] row-major (attn @ V)
// Optional batching over blockIdx.z with (b, h) decomposition (Hdim > 0).
// ---------------------------------------------------------------------------
template<int BM, int BN, int BK, int TM, int TN, bool B_KN>
__global__ __launch_bounds__((BM/TM)*(BN/TN))
void gemm_kernel(const float* __restrict__ A, int lda, long sAb, long sAh,
                 const float* __restrict__ Bp, int ldb, long sBb, long sBh,
                 const float* __restrict__ bias,
                 const float* __restrict__ resid, int ldr,
                 float* __restrict__ C, int ldc, long sCb, long sCh,
                 int K, float scale, int do_relu, int Hdim)
{
    __shared__ __align__(16) float As[BK][BM];
    __shared__ __align__(16) float Bs[BK][BN];

    if (Hdim > 0) {
        int z  = blockIdx.z;
        int bb = z / Hdim;
        int hh = z % Hdim;
        A  += bb * sAb + hh * sAh;
        Bp += bb * sBb + hh * sBh;
        C  += bb * sCb + hh * sCh;
    }

    const int m0  = blockIdx.y * BM;
    const int n0  = blockIdx.x * BN;
    const int tid = threadIdx.x;
    constexpr int NT = (BM/TM) * (BN/TN);
    const int tx = tid % (BN / TN);
    const int ty = tid / (BN / TN);

    float acc[TM][TN];
#pragma unroll
    for (int i = 0; i < TM; i++)
#pragma unroll
        for (int j = 0; j < TN; j++) acc[i][j] = 0.f;

    constexpr int KV4 = BK / 4;         // float4 per K-row chunk
    constexpr int AV4 = BM * KV4;       // float4 loads for A tile

    for (int k0 = 0; k0 < K; k0 += BK) {
        // --- load A tile [BM x BK], transpose into As[BK][BM] ---
#pragma unroll
        for (int f = tid; f < AV4; f += NT) {
            int row = f / KV4;
            int cv  = f % KV4;
            float4 v = *reinterpret_cast<const float4*>(
                &A[(long)(m0 + row) * lda + k0 + cv * 4]);
            As[cv*4+0][row] = v.x;
            As[cv*4+1][row] = v.y;
            As[cv*4+2][row] = v.z;
            As[cv*4+3][row] = v.w;
        }
        // --- load B tile ---
        if constexpr (!B_KN) {
            constexpr int BV4 = BN * KV4;
#pragma unroll
            for (int f = tid; f < BV4; f += NT) {
                int row = f / KV4;
                int cv  = f % KV4;
                float4 v = *reinterpret_cast<const float4*>(
                    &Bp[(long)(n0 + row) * ldb + k0 + cv * 4]);
                Bs[cv*4+0][row] = v.x;
                Bs[cv*4+1][row] = v.y;
                Bs[cv*4+2][row] = v.z;
                Bs[cv*4+3][row] = v.w;
            }
        } else {
            constexpr int NV4 = BN / 4;
#pragma unroll
            for (int f = tid; f < BK * NV4; f += NT) {
                int row = f / NV4;   // k within tile
                int cv  = f % NV4;
                float4 v = *reinterpret_cast<const float4*>(
                    &Bp[(long)(k0 + row) * ldb + n0 + cv * 4]);
                *reinterpret_cast<float4*>(&Bs[row][cv * 4]) = v;
            }
        }
        __syncthreads();

#pragma unroll
        for (int kk = 0; kk < BK; kk++) {
            float a[TM], b[TN];
#pragma unroll
            for (int i = 0; i < TM; i++) a[i] = As[kk][ty * TM + i];
#pragma unroll
            for (int j = 0; j < TN; j++) b[j] = Bs[kk][tx * TN + j];
#pragma unroll
            for (int i = 0; i < TM; i++)
#pragma unroll
                for (int j = 0; j < TN; j++)
                    acc[i][j] = fmaf(a[i], b[j], acc[i][j]);
        }
        __syncthreads();
    }

    // --- epilogue ---
#pragma unroll
    for (int i = 0; i < TM; i++) {
        int m = m0 + ty * TM + i;
#pragma unroll
        for (int j = 0; j < TN; j++) {
            int n = n0 + tx * TN + j;
            float v = acc[i][j] * scale;
            if (bias)  v += bias[n];
            if (resid) v += resid[(long)m * ldr + n];
            if (do_relu) v = fmaxf(v, 0.f);
            C[(long)m * ldc + n] = v;
        }
    }
}

// ---------------------------------------------------------------------------
// Row softmax over last dim (1024), in place. One block (256 thr) per row.
// ---------------------------------------------------------------------------
__global__ void softmax_kernel(float* __restrict__ sc)
{
    __shared__ float red[8];
    const long row = blockIdx.x;
    float* p = sc + row * (long)SEQ;
    const int tid = threadIdx.x;

    float4 x = reinterpret_cast<float4*>(p)[tid];
    float m = fmaxf(fmaxf(x.x, x.y), fmaxf(x.z, x.w));
#pragma unroll
    for (int o = 16; o > 0; o >>= 1) m = fmaxf(m, __shfl_xor_sync(~0u, m, o));
    if ((tid & 31) == 0) red[tid >> 5] = m;
    __syncthreads();
    float mm = red[0];
#pragma unroll
    for (int i = 1; i < 8; i++) mm = fmaxf(mm, red[i]);

    float e0 = __expf(x.x - mm), e1 = __expf(x.y - mm);
    float e2 = __expf(x.z - mm), e3 = __expf(x.w - mm);
    float s = e0 + e1 + e2 + e3;
#pragma unroll
    for (int o = 16; o > 0; o >>= 1) s += __shfl_xor_sync(~0u, s, o);
    __syncthreads();
    if ((tid & 31) == 0) red[tid >> 5] = s;
    __syncthreads();
    float ss = 0.f;
#pragma unroll
    for (int i = 0; i < 8; i++) ss += red[i];
    float inv = 1.f / ss;
    x.x = e0 * inv; x.y = e1 * inv; x.z = e2 * inv; x.w = e3 * inv;
    reinterpret_cast<float4*>(p)[tid] = x;
}

// ---------------------------------------------------------------------------
// LayerNorm over last dim (1024). One block (256 thr) per row.
// ---------------------------------------------------------------------------
__global__ void layernorm_kernel(const float* __restrict__ in,
                                 const float* __restrict__ g,
                                 const float* __restrict__ b,
                                 float* __restrict__ out)
{
    __shared__ float rs[8], rq[8];
    const long row = blockIdx.x;
    const int tid = threadIdx.x;
    float4 x = reinterpret_cast<const float4*>(in + row * (long)DM)[tid];

    float s = x.x + x.y + x.z + x.w;
    float q = x.x*x.x + x.y*x.y + x.z*x.z + x.w*x.w;
#pragma unroll
    for (int o = 16; o > 0; o >>= 1) {
        s += __shfl_xor_sync(~0u, s, o);
        q += __shfl_xor_sync(~0u, q, o);
    }
    if ((tid & 31) == 0) { rs[tid >> 5] = s; rq[tid >> 5] = q; }
    __syncthreads();
    float ts = 0.f, tq = 0.f;
#pragma unroll
    for (int i = 0; i < 8; i++) { ts += rs[i]; tq += rq[i]; }

    const float mu  = ts * (1.f / DM);
    const float var = tq * (1.f / DM) - mu * mu;
    const float r   = rsqrtf(var + EPS);

    float4 gg = reinterpret_cast<const float4*>(g)[tid];
    float4 bb = reinterpret_cast<const float4*>(b)[tid];
    float4 y;
    y.x = (x.x - mu) * r * gg.x + bb.x;
    y.y = (x.y - mu) * r * gg.y + bb.y;
    y.z = (x.z - mu) * r * gg.z + bb.z;
    y.w = (x.w - mu) * r * gg.w + bb.w;
    reinterpret_cast<float4*>(out + row * (long)DM)[tid] = y;
}

// ---------------------------------------------------------------------------
// Host launch
// ---------------------------------------------------------------------------
extern "C" void kernel_launch(void* const* d_in, const int* in_sizes, int n_in,
                              void* d_out, int out_size)
{
    (void)in_sizes; (void)n_in; (void)out_size;
    const float* src       = (const float*)d_in[0];
    const float* in_proj_w = (const float*)d_in[1];
    const float* in_proj_b = (const float*)d_in[2];
    const float* out_w     = (const float*)d_in[3];
    const float* out_b     = (const float*)d_in[4];
    const float* w1        = (const float*)d_in[5];
    const float* b1        = (const float*)d_in[6];
    const float* w2        = (const float*)d_in[7];
    const float* b2        = (const float*)d_in[8];
    const float* g1        = (const float*)d_in[9];
    const float* be1       = (const float*)d_in[10];
    const float* g2        = (const float*)d_in[11];
    const float* be2       = (const float*)d_in[12];
    float* out = (float*)d_out;

    void *vp;
    float *p_qkv, *p_scores, *p_ctx, *p_x, *p_h1, *p_tmp;
    cudaGetSymbolAddress(&vp, g_qkv);    p_qkv    = (float*)vp;
    cudaGetSymbolAddress(&vp, g_scores); p_scores = (float*)vp;
    cudaGetSymbolAddress(&vp, g_ctx);    p_ctx    = (float*)vp;
    cudaGetSymbolAddress(&vp, g_x);      p_x      = (float*)vp;
    cudaGetSymbolAddress(&vp, g_h1);     p_h1     = (float*)vp;
    cudaGetSymbolAddress(&vp, g_tmp);    p_tmp    = (float*)vp;

    const int LDQKV = 3 * DM;           // 3072
    const int LDBIG = BATCH * 3 * DM;   // 24576, stride over s for q/k/v views

    // 1) QKV = src @ in_proj_w^T + in_proj_b   -> g_qkv [8192, 3072]
    {
        dim3 grid(3 * DM / 128, SB / 128, 1);
        gemm_kernel<128,128,16,8,8,false><<<grid, 256>>>(
            src, DM, 0, 0,
            in_proj_w, DM, 0, 0,
            in_proj_b, nullptr, 0,
            p_qkv, LDQKV, 0, 0,
            DM, 1.f, 0, 0);
    }

    // 2) scores[b,h,s,t] = scale * q[s] . k[t]   (batched over b*h = 128)
    {
        dim3 grid(SEQ / 128, SEQ / 128, BATCH * NH);
        gemm_kernel<128,128,16,8,8,false><<<grid, 256>>>(
            p_qkv,       LDBIG, (long)3 * DM, (long)HD,    // q view
            p_qkv + DM,  LDBIG, (long)3 * DM, (long)HD,    // k view
            nullptr, nullptr, 0,
            p_scores, SEQ, (long)NH * SEQ * SEQ, (long)SEQ * SEQ,
            HD, 0.125f /* 1/sqrt(64) */, 0, NH);
    }

    // 3) softmax over t
    softmax_kernel<<<BATCH * NH * SEQ, 256>>>(p_scores);

    // 4) ctx[s,b,h*64+d] = attn @ v   (batched, B is [K,N])
    {
        dim3 grid(1, SEQ / 128, BATCH * NH);
        gemm_kernel<128,64,16,8,4,true><<<grid, 256>>>(
            p_scores, SEQ, (long)NH * SEQ * SEQ, (long)SEQ * SEQ,
            p_qkv + 2 * DM, LDBIG, (long)3 * DM, (long)HD,  // v view
            nullptr, nullptr, 0,
            p_ctx, BATCH * DM, (long)DM, (long)HD,
            SEQ, 1.f, 0, NH);
    }

    // 5) tmp = ctx @ out_w^T + out_b + src
    {
        dim3 grid(DM / 128, SB / 128, 1);
        gemm_kernel<128,128,16,8,8,false><<<grid, 256>>>(
            p_ctx, DM, 0, 0,
            out_w, DM, 0, 0,
            out_b, src, DM,
            p_tmp, DM, 0, 0,
            DM, 1.f, 0, 0);
    }

    // 6) x = LN1(tmp)
    layernorm_kernel<<<SB, 256>>>(p_tmp, g1, be1, p_x);

    // 7) h1 = relu(x @ w1^T + b1)
    {
        dim3 grid(FF / 128, SB / 128, 1);
        gemm_kernel<128,128,16,8,8,false><<<grid, 256>>>(
            p_x, DM, 0, 0,
            w1, DM, 0, 0,
            b1, nullptr, 0,
            p_h1, FF, 0, 0,
            DM, 1.f, 1, 0);
    }

    // 8) tmp = h1 @ w2^T + b2 + x
    {
        dim3 grid(DM / 128, SB / 128, 1);
        gemm_kernel<128,128,16,8,8,false><<<grid, 256>>>(
            p_h1, FF, 0, 0,
            w2, FF, 0, 0,
            b2, p_x, DM,
            p_tmp, DM, 0, 0,
            FF, 1.f, 0, 0);
    }

    // 9) out = LN2(tmp)
    layernorm_kernel<<<SB, 256>>>(p_tmp, g2, be2, out);
}

// round 4
// speedup vs baseline: 2.1663x; 2.1663x over previous
#include <cuda_runtime.h>
#include <cuda_bf16.h>
#include <cstdint>

typedef __nv_bfloat16 bf16;
constexpr int SEQ = 1024, BATCH = 8, DM = 1024, NH = 16, HD = 64, FF = 4096;
constexpr int SB = SEQ * BATCH;
constexpr float EPS = 1e-5f;

// ---------------- scratch (device globals; no allocation allowed) ----------
__device__ float g_qkv[(size_t)SB * 3 * DM];
__device__ float g_scores[(size_t)BATCH * NH * SEQ * SEQ];
__device__ float g_ctx[(size_t)SB * DM];
__device__ float g_x[(size_t)SB * DM];
__device__ float g_h1[(size_t)SB * FF];
__device__ float g_tmp[(size_t)SB * DM];

__device__ bf16 g_srcH[(size_t)SB * DM],  g_srcL[(size_t)SB * DM];
__device__ bf16 g_wiH[(size_t)3 * DM * DM], g_wiL[(size_t)3 * DM * DM];
__device__ bf16 g_owH[(size_t)DM * DM],   g_owL[(size_t)DM * DM];
__device__ bf16 g_w1H[(size_t)FF * DM],   g_w1L[(size_t)FF * DM];
__device__ bf16 g_w2H[(size_t)DM * FF],   g_w2L[(size_t)DM * FF];
__device__ bf16 g_qH[(size_t)BATCH*NH*SEQ*HD], g_qL[(size_t)BATCH*NH*SEQ*HD];
__device__ bf16 g_kH[(size_t)BATCH*NH*SEQ*HD], g_kL[(size_t)BATCH*NH*SEQ*HD];
__device__ bf16 g_vtH[(size_t)BATCH*NH*HD*SEQ], g_vtL[(size_t)BATCH*NH*HD*SEQ];
__device__ bf16 g_atH[(size_t)BATCH*NH*SEQ*SEQ], g_atL[(size_t)BATCH*NH*SEQ*SEQ];
__device__ bf16 g_ctxH[(size_t)SB * DM],  g_ctxL[(size_t)SB * DM];
__device__ bf16 g_xH[(size_t)SB * DM],    g_xL[(size_t)SB * DM];
__device__ bf16 g_h1H[(size_t)SB * FF],   g_h1L[(size_t)SB * FF];

// ---------------- helpers ---------------------------------------------------
__device__ __forceinline__ uint32_t smem_u32(const void* p) {
    uint32_t a;
    asm("{ .reg .u64 t; cvta.to.shared.u64 t, %1; cvt.u32.u64 %0, t; }" : "=r"(a) : "l"(p));
    return a;
}
__device__ __forceinline__ void cp16(uint32_t saddr, const void* gaddr) {
    asm volatile("cp.async.cg.shared.global [%0], [%1], 16;" :: "r"(saddr), "l"(gaddr));
}
__device__ __forceinline__ void cp_commit() { asm volatile("cp.async.commit_group;"); }
__device__ __forceinline__ void cp_wait1()  { asm volatile("cp.async.wait_group 1;"); }
__device__ __forceinline__ void cp_wait0()  { asm volatile("cp.async.wait_group 0;"); }
__device__ __forceinline__ void ldm_x4(uint32_t& r0, uint32_t& r1, uint32_t& r2, uint32_t& r3,
                                       uint32_t addr) {
    asm volatile("ldmatrix.sync.aligned.m8n8.x4.shared.b16 {%0,%1,%2,%3}, [%4];"
                 : "=r"(r0), "=r"(r1), "=r"(r2), "=r"(r3) : "r"(addr));
}
__device__ __forceinline__ void mma16816(float* c, const uint32_t* a, uint32_t b0, uint32_t b1) {
    asm volatile("mma.sync.aligned.m16n8k16.row.col.f32.bf16.bf16.f32 "
                 "{%0,%1,%2,%3}, {%4,%5,%6,%7}, {%8,%9}, {%0,%1,%2,%3};"
                 : "+f"(c[0]), "+f"(c[1]), "+f"(c[2]), "+f"(c[3])
                 : "r"(a[0]), "r"(a[1]), "r"(a[2]), "r"(a[3]), "r"(b0), "r"(b1));
}
__device__ __forceinline__ void split_hl(float x, bf16& h, bf16& l) {
    h = __float2bfloat16(x);
    l = __float2bfloat16(x - __bfloat162float(h));
}

// ---------------------------------------------------------------------------
// bf16 HMMA GEMM with 3-segment split accumulation.
//   C[m,n] = sum over segs { A_seg[m,k] * B_seg[n,k] }   (both row-major, K contig)
//   seg0: (Ah,Bh)  seg1: (Ah,Bl)  seg2: (Al,Bh)
// BM = 128, BK = 64. 256 threads, warp grid 2(m) x 4(n), warp tile 64 x BN/4.
// smem: A [2][128][64] + B [2][BN][64], 16B-chunk xor swizzle (c ^= r&7).
// ---------------------------------------------------------------------------
template<int BN>
__global__ __launch_bounds__(256, 1)
void gemm_mma(const bf16* __restrict__ Ah, const bf16* __restrict__ Al, int lda, long sA,
              const bf16* __restrict__ Bh, const bf16* __restrict__ Bl, int ldb, long sB,
              const float* __restrict__ bias, const float* __restrict__ resid,
              float* __restrict__ C, int ldc, long sCb, long sCh, int Hdim,
              int K, int relu)
{
    extern __shared__ char smem[];
    const uint32_t sbase = smem_u32(smem);
    constexpr int ASTG = 128 * 128;        // bytes per A stage (128 rows x 128B)
    constexpr int BSTG = BN * 128;
    const uint32_t aS = sbase;
    const uint32_t bS = sbase + 2 * ASTG;
    constexpr int NI = BN / 32;            // n-frags per warp (8 cols each)

    const int tid = threadIdx.x, wid = tid >> 5, lane = tid & 31;
    const int wm = wid >> 2, wn = wid & 3;

    if (gridDim.z > 1) {
        long z = blockIdx.z;
        Ah += z * sA; Al += z * sA;
        Bh += z * sB; Bl += z * sB;
        C  += (z / Hdim) * sCb + (z % Hdim) * sCh;
    }
    const long m0 = (long)blockIdx.y * 128;
    const long n0 = (long)blockIdx.x * BN;

    const int tps = K >> 6;
    const int nt  = 3 * tps;

    float acc[4][NI][4];
#pragma unroll
    for (int i = 0; i < 4; i++)
#pragma unroll
        for (int j = 0; j < NI; j++)
#pragma unroll
            for (int q = 0; q < 4; q++) acc[i][j][q] = 0.f;

    // ---- tile loader (cp.async) ----
    auto load_tile = [&](int i, int st) {
        const int seg = i / tps;
        const long k0 = (long)(i - seg * tps) << 6;
        const bf16* Ap = ((seg == 2) ? Al : Ah);
        const bf16* Bp = ((seg == 1) ? Bl : Bh);
#pragma unroll
        for (int it = 0; it < 4; it++) {                 // A: 1024 chunks
            int f = tid + it * 256, r = f >> 3, c = f & 7;
            cp16(aS + st * ASTG + r * 128 + ((c ^ (r & 7)) << 4),
                 Ap + (m0 + r) * (long)lda + k0 + c * 8);
        }
#pragma unroll
        for (int it = 0; it < BN / 32; it++) {           // B: BN*8 chunks
            int f = tid + it * 256, r = f >> 3, c = f & 7;
            cp16(bS + st * BSTG + r * 128 + ((c ^ (r & 7)) << 4),
                 Bp + (n0 + r) * (long)ldb + k0 + c * 8);
        }
        cp_commit();
    };

    load_tile(0, 0);

    for (int i = 0; i < nt; i++) {
        const int st = i & 1;
        if (i + 1 < nt) { load_tile(i + 1, st ^ 1); cp_wait1(); }
        else            { cp_wait0(); }
        __syncthreads();

        const uint32_t aB = aS + st * ASTG;
        const uint32_t bB = bS + st * BSTG;
#pragma unroll
        for (int ks = 0; ks < 4; ks++) {
            uint32_t af[4][4];
#pragma unroll
            for (int mi = 0; mi < 4; mi++) {
                int r = wm * 64 + mi * 16 + (lane & 15);
                int c = ks * 2 + (lane >> 4);
                ldm_x4(af[mi][0], af[mi][1], af[mi][2], af[mi][3],
                       aB + r * 128 + ((c ^ (r & 7)) << 4));
            }
            uint32_t bfr[NI][2];
#pragma unroll
            for (int p = 0; p < NI / 2; p++) {
                int n = wn * (BN / 4) + p * 16 + (lane & 7) + ((lane >> 4) << 3);
                int c = ks * 2 + ((lane >> 3) & 1);
                uint32_t r0, r1, r2, r3;
                ldm_x4(r0, r1, r2, r3, bB + n * 128 + ((c ^ (n & 7)) << 4));
                bfr[2*p][0] = r0; bfr[2*p][1] = r1;
                bfr[2*p+1][0] = r2; bfr[2*p+1][1] = r3;
            }
#pragma unroll
            for (int mi = 0; mi < 4; mi++)
#pragma unroll
                for (int ni = 0; ni < NI; ni++)
                    mma16816(acc[mi][ni], af[mi], bfr[ni][0], bfr[ni][1]);
        }
        __syncthreads();
    }

    // ---- epilogue ----
    const long mw = m0 + wm * 64;
    const long nw = n0 + wn * (BN / 4);
#pragma unroll
    for (int mi = 0; mi < 4; mi++) {
#pragma unroll
        for (int ni = 0; ni < NI; ni++) {
            float* c = acc[mi][ni];
            long r0 = mw + mi * 16 + (lane >> 2);
            long cc = nw + ni * 8 + (lane & 3) * 2;
            float2 v0 = make_float2(c[0], c[1]);
            float2 v1 = make_float2(c[2], c[3]);
            if (bias) {
                float2 bv = *reinterpret_cast<const float2*>(bias + cc);
                v0.x += bv.x; v0.y += bv.y; v1.x += bv.x; v1.y += bv.y;
            }
            if (resid) {
                float2 ra = *reinterpret_cast<const float2*>(resid + r0 * ldc + cc);
                float2 rb = *reinterpret_cast<const float2*>(resid + (r0 + 8) * ldc + cc);
                v0.x += ra.x; v0.y += ra.y; v1.x += rb.x; v1.y += rb.y;
            }
            if (relu) {
                v0.x = fmaxf(v0.x, 0.f); v0.y = fmaxf(v0.y, 0.f);
                v1.x = fmaxf(v1.x, 0.f); v1.y = fmaxf(v1.y, 0.f);
            }
            *reinterpret_cast<float2*>(C + r0 * ldc + cc) = v0;
            *reinterpret_cast<float2*>(C + (r0 + 8) * ldc + cc) = v1;
        }
    }
}

// ---------------- conversions ----------------------------------------------
__global__ void split2(const float* __restrict__ in, bf16* __restrict__ hi,
                       bf16* __restrict__ lo, long n4)
{
    long i = (long)blockIdx.x * blockDim.x + threadIdx.x;
    if (i >= n4) return;
    float4 v = reinterpret_cast<const float4*>(in)[i];
    bf16 h[4], l[4];
    split_hl(v.x, h[0], l[0]); split_hl(v.y, h[1], l[1]);
    split_hl(v.z, h[2], l[2]); split_hl(v.w, h[3], l[3]);
    reinterpret_cast<uint2*>(hi)[i] = *reinterpret_cast<uint2*>(h);
    reinterpret_cast<uint2*>(lo)[i] = *reinterpret_cast<uint2*>(l);
}

// qkv fp32 [row=s*8+b, 3072] -> q,k bf16 [z=b*16+h, s, 64]  (q pre-scaled)
__global__ void qk_split(const float* __restrict__ qkv,
                         bf16* __restrict__ qH, bf16* __restrict__ qL,
                         bf16* __restrict__ kH, bf16* __restrict__ kL)
{
    long idx = (long)blockIdx.x * 256 + threadIdx.x;
    int row = (int)(idx >> 10), c = (int)(idx & 1023);
    int s = row >> 3, b = row & 7, h = c >> 6, d = c & 63;
    float qv = qkv[(long)row * 3072 + c] * 0.125f;
    float kv = qkv[(long)row * 3072 + 1024 + c];
    long o = (((long)(b * 16 + h)) * 1024 + s) * 64 + d;
    bf16 hh, ll;
    split_hl(qv, hh, ll); qH[o] = hh; qL[o] = ll;
    split_hl(kv, hh, ll); kH[o] = hh; kL[o] = ll;
}

// v from qkv -> vt bf16 [z, d, t]
__global__ void v_split(const float* __restrict__ qkv,
                        bf16* __restrict__ vtH, bf16* __restrict__ vtL)
{
    int bx = blockIdx.x;
    int z = bx >> 7, tb = bx & 127;
    int b = z >> 4, h = z & 15, d = threadIdx.x;
    bf16 hs[8], ls[8];
#pragma unroll
    for (int tt = 0; tt < 8; tt++) {
        int t = tb * 8 + tt;
        float v = qkv[((long)(t * 8 + b)) * 3072 + 2048 + h * 64 + d];
        split_hl(v, hs[tt], ls[tt]);
    }
    long o = ((long)(z * 64 + d)) * 1024 + tb * 8;
    *reinterpret_cast<uint4*>(vtH + o) = *reinterpret_cast<uint4*>(hs);
    *reinterpret_cast<uint4*>(vtL + o) = *reinterpret_cast<uint4*>(ls);
}

// softmax over scores row (1024) -> attn hi/lo bf16
__global__ void softmax_bf(const float* __restrict__ sc,
                           bf16* __restrict__ aH, bf16* __restrict__ aL)
{
    __shared__ float red[8];
    const long row = blockIdx.x;
    const float* p = sc + row * (long)SEQ;
    const int tid = threadIdx.x;
    float4 x = reinterpret_cast<const float4*>(p)[tid];
    float m = fmaxf(fmaxf(x.x, x.y), fmaxf(x.z, x.w));
#pragma unroll
    for (int o = 16; o > 0; o >>= 1) m = fmaxf(m, __shfl_xor_sync(~0u, m, o));
    if ((tid & 31) == 0) red[tid >> 5] = m;
    __syncthreads();
    float mm = red[0];
#pragma unroll
    for (int i = 1; i < 8; i++) mm = fmaxf(mm, red[i]);
    float e0 = __expf(x.x - mm), e1 = __expf(x.y - mm);
    float e2 = __expf(x.z - mm), e3 = __expf(x.w - mm);
    float s = e0 + e1 + e2 + e3;
#pragma unroll
    for (int o = 16; o > 0; o >>= 1) s += __shfl_xor_sync(~0u, s, o);
    __syncthreads();
    if ((tid & 31) == 0) red[tid >> 5] = s;
    __syncthreads();
    float ss = 0.f;
#pragma unroll
    for (int i = 0; i < 8; i++) ss += red[i];
    float inv = 1.f / ss;
    bf16 h[4], l[4];
    split_hl(e0 * inv, h[0], l[0]); split_hl(e1 * inv, h[1], l[1]);
    split_hl(e2 * inv, h[2], l[2]); split_hl(e3 * inv, h[3], l[3]);
    reinterpret_cast<uint2*>(aH + row * (long)SEQ)[tid] = *reinterpret_cast<uint2*>(h);
    reinterpret_cast<uint2*>(aL + row * (long)SEQ)[tid] = *reinterpret_cast<uint2*>(l);
}

__global__ void layernorm_kernel(const float* __restrict__ in, const float* __restrict__ g,
                                 const float* __restrict__ b, float* __restrict__ out)
{
    __shared__ float rs[8], rq[8];
    const long row = blockIdx.x;
    const int tid = threadIdx.x;
    float4 x = reinterpret_cast<const float4*>(in + row * (long)DM)[tid];
    float s = x.x + x.y + x.z + x.w;
    float q = x.x*x.x + x.y*x.y + x.z*x.z + x.w*x.w;
#pragma unroll
    for (int o = 16; o > 0; o >>= 1) {
        s += __shfl_xor_sync(~0u, s, o);
        q += __shfl_xor_sync(~0u, q, o);
    }
    if ((tid & 31) == 0) { rs[tid >> 5] = s; rq[tid >> 5] = q; }
    __syncthreads();
    float ts = 0.f, tq = 0.f;
#pragma unroll
    for (int i = 0; i < 8; i++) { ts += rs[i]; tq += rq[i]; }
    const float mu = ts * (1.f / DM);
    const float var = tq * (1.f / DM) - mu * mu;
    const float r = rsqrtf(var + EPS);
    float4 gg = reinterpret_cast<const float4*>(g)[tid];
    float4 bb = reinterpret_cast<const float4*>(b)[tid];
    float4 y;
    y.x = (x.x - mu) * r * gg.x + bb.x;
    y.y = (x.y - mu) * r * gg.y + bb.y;
    y.z = (x.z - mu) * r * gg.z + bb.z;
    y.w = (x.w - mu) * r * gg.w + bb.w;
    reinterpret_cast<float4*>(out + row * (long)DM)[tid] = y;
}

// ---------------- host ------------------------------------------------------
#define SYMADDR(p, s) do { void* v_; cudaGetSymbolAddress(&v_, s); p = (decltype(p))v_; } while (0)

extern "C" void kernel_launch(void* const* d_in, const int* in_sizes, int n_in,
                              void* d_out, int out_size)
{
    (void)in_sizes; (void)n_in; (void)out_size;
    const float* src = (const float*)d_in[0];
    const float* in_proj_w = (const float*)d_in[1];
    const float* in_proj_b = (const float*)d_in[2];
    const float* out_w = (const float*)d_in[3];
    const float* out_b = (const float*)d_in[4];
    const float* w1 = (const float*)d_in[5];
    const float* b1 = (const float*)d_in[6];
    const float* w2 = (const float*)d_in[7];
    const float* b2 = (const float*)d_in[8];
    const float* g1 = (const float*)d_in[9];
    const float* be1 = (const float*)d_in[10];
    const float* g2 = (const float*)d_in[11];
    const float* be2 = (const float*)d_in[12];
    float* out = (float*)d_out;

    float *p_qkv, *p_scores, *p_ctx, *p_x, *p_h1, *p_tmp;
    bf16 *srcH, *srcL, *wiH, *wiL, *owH, *owL, *w1H, *w1L, *w2H, *w2L;
    bf16 *qH, *qL, *kH, *kL, *vtH, *vtL, *atH, *atL, *ctxH, *ctxL, *xH, *xL, *h1H, *h1L;
    SYMADDR(p_qkv, g_qkv); SYMADDR(p_scores, g_scores); SYMADDR(p_ctx, g_ctx);
    SYMADDR(p_x, g_x); SYMADDR(p_h1, g_h1); SYMADDR(p_tmp, g_tmp);
    SYMADDR(srcH, g_srcH); SYMADDR(srcL, g_srcL);
    SYMADDR(wiH, g_wiH); SYMADDR(wiL, g_wiL);
    SYMADDR(owH, g_owH); SYMADDR(owL, g_owL);
    SYMADDR(w1H, g_w1H); SYMADDR(w1L, g_w1L);
    SYMADDR(w2H, g_w2H); SYMADDR(w2L, g_w2L);
    SYMADDR(qH, g_qH); SYMADDR(qL, g_qL); SYMADDR(kH, g_kH); SYMADDR(kL, g_kL);
    SYMADDR(vtH, g_vtH); SYMADDR(vtL, g_vtL);
    SYMADDR(atH, g_atH); SYMADDR(atL, g_atL);
    SYMADDR(ctxH, g_ctxH); SYMADDR(ctxL, g_ctxL);
    SYMADDR(xH, g_xH); SYMADDR(xL, g_xL);
    SYMADDR(h1H, g_h1H); SYMADDR(h1L, g_h1L);

    const int SM128 = 2 * (128 * 128) + 2 * (128 * 128);   // 64 KB
    const int SM64  = 2 * (128 * 128) + 2 * (64 * 128);    // 48 KB
    cudaFuncSetAttribute(gemm_mma<128>, cudaFuncAttributeMaxDynamicSharedMemorySize, SM128);
    cudaFuncSetAttribute(gemm_mma<64>,  cudaFuncAttributeMaxDynamicSharedMemorySize, SM64);

    auto spl = [](const float* in, bf16* h, bf16* l, long n) {
        long n4 = n >> 2;
        split2<<<(unsigned)((n4 + 255) / 256), 256>>>(in, h, l, n4);
    };

    // weight + src splits
    spl(src, srcH, srcL, (long)SB * DM);
    spl(in_proj_w, wiH, wiL, (long)3 * DM * DM);
    spl(out_w, owH, owL, (long)DM * DM);
    spl(w1, w1H, w1L, (long)FF * DM);
    spl(w2, w2H, w2L, (long)DM * FF);

    // 1) QKV = src @ in_proj_w^T + b
    gemm_mma<128><<<dim3(24, 64, 1), 256, SM128>>>(
        srcH, srcL, DM, 0, wiH, wiL, DM, 0,
        in_proj_b, nullptr, p_qkv, 3 * DM, 0, 0, 1, DM, 0);

    // 2) head-major splits of q, k, v^T
    qk_split<<<SB * DM / 256, 256>>>(p_qkv, qH, qL, kH, kL);
    v_split<<<BATCH * NH * 128, 64>>>(p_qkv, vtH, vtL);

    // 3) scores = q @ k^T  (batched over 128 heads)
    gemm_mma<128><<<dim3(8, 8, BATCH * NH), 256, SM128>>>(
        qH, qL, HD, (long)SEQ * HD, kH, kL, HD, (long)SEQ * HD,
        nullptr, nullptr, p_scores, SEQ, (long)SEQ * SEQ, 0, 1, HD, 0);

    // 4) softmax -> attn hi/lo
    softmax_bf<<<BATCH * NH * SEQ, 256>>>(p_scores, atH, atL);

    // 5) ctx = attn @ v  (batched; C scattered into [s, b*1024+h*64+d])
    gemm_mma<64><<<dim3(1, 8, BATCH * NH), 256, SM64>>>(
        atH, atL, SEQ, (long)SEQ * SEQ, vtH, vtL, SEQ, (long)HD * SEQ,
        nullptr, nullptr, p_ctx, BATCH * DM, (long)DM, (long)HD, NH, SEQ, 0);

    // 6) tmp = ctx @ out_w^T + out_b + src ; x = LN1
    spl(p_ctx, ctxH, ctxL, (long)SB * DM);
    gemm_mma<128><<<dim3(8, 64, 1), 256, SM128>>>(
        ctxH, ctxL, DM, 0, owH, owL, DM, 0,
        out_b, src, p_tmp, DM, 0, 0, 1, DM, 0);
    layernorm_kernel<<<SB, 256>>>(p_tmp, g1, be1, p_x);

    // 7) FFN
    spl(p_x, xH, xL, (long)SB * DM);
    gemm_mma<128><<<dim3(32, 64, 1), 256, SM128>>>(
        xH, xL, DM, 0, w1H, w1L, DM, 0,
        b1, nullptr, p_h1, FF, 0, 0, 1, DM, 1);
    spl(p_h1, h1H, h1L, (long)SB * FF);
    gemm_mma<128><<<dim3(8, 64, 1), 256, SM128>>>(
        h1H, h1L, FF, 0, w2H, w2L, FF, 0,
        b2, p_x, p_tmp, DM, 0, 0, 1, FF, 0);

    // 8) out = LN2
    layernorm_kernel<<<SB, 256>>>(p_tmp, g2, be2, out);
}